// round 11
// baseline (speedup 1.0000x reference)
#include <cuda_runtime.h>

#define B_   32
#define N_   512
#define M_   512
#define D_   64
#define KD   (N_ + M_ - 1)          // 1023 anti-diagonals of the D matrix
#define BIGF 1e10f
#define INV_LN2 1.4426950408889634f
#define LN2     0.6931471805599453f
#define BIGQ (BIGF * INV_LN2)

// Tiled diag-major distances, pre-scaled by 1/ln2:
//   g_Dt[((b*32 + kD/32)*16 + row/32)*1024 + (kD%32)*32 + (row%32)]
// where row = i-1 (0..511), kD = (i-1)+(j-1) (0..1022; slot 1023 padding).
__device__ float g_Dt[(size_t)B_ * 32 * 16 * 1024];   // 64 MB static scratch

__device__ __forceinline__ float ex2f(float x) {
    float y; asm("ex2.approx.ftz.f32 %0, %1;" : "=f"(y) : "f"(x)); return y;
}
__device__ __forceinline__ float lg2f(float x) {
    float y; asm("lg2.approx.ftz.f32 %0, %1;" : "=f"(y) : "f"(x)); return y;
}

// ---------------------------------------------------------------------------
// Kernel 1: distance tiles, drained into the TILED diag-major layout.
// (unchanged from R8)
// ---------------------------------------------------------------------------
#define TS  64
#define SP  68
#define TSP 66

__global__ __launch_bounds__(256) void dist_kernel(const float* __restrict__ x,
                                                   const float* __restrict__ y) {
    __shared__ float Xs[D_ * SP];
    __shared__ float Ys[D_ * SP];
    __shared__ float xn[TS], yn[TS];

    const int b  = blockIdx.z;
    const int i0 = blockIdx.y * TS;
    const int j0 = blockIdx.x * TS;
    const float* xb = x + ((size_t)b * N_ + i0) * D_;
    const float* yb = y + ((size_t)b * M_ + j0) * D_;
    const int tid = threadIdx.x;

#pragma unroll
    for (int it = 0; it < 4; ++it) {
        int f   = tid + it * 256;
        int row = f & 63;
        int c4  = f >> 6;
        float4 vx = *(const float4*)(xb + row * D_ + c4 * 4);
        float4 vy = *(const float4*)(yb + row * D_ + c4 * 4);
        Xs[(c4 * 4 + 0) * SP + row] = vx.x;
        Xs[(c4 * 4 + 1) * SP + row] = vx.y;
        Xs[(c4 * 4 + 2) * SP + row] = vx.z;
        Xs[(c4 * 4 + 3) * SP + row] = vx.w;
        Ys[(c4 * 4 + 0) * SP + row] = vy.x;
        Ys[(c4 * 4 + 1) * SP + row] = vy.y;
        Ys[(c4 * 4 + 2) * SP + row] = vy.z;
        Ys[(c4 * 4 + 3) * SP + row] = vy.w;
    }
    __syncthreads();

    if (tid < 64) {
        float s = 0.f;
#pragma unroll
        for (int k = 0; k < D_; ++k) { float v = Xs[k * SP + tid]; s = fmaf(v, v, s); }
        xn[tid] = s;
    } else if (tid < 128) {
        int r = tid - 64;
        float s = 0.f;
#pragma unroll
        for (int k = 0; k < D_; ++k) { float v = Ys[k * SP + r]; s = fmaf(v, v, s); }
        yn[r] = s;
    }
    __syncthreads();

    const int tx = tid & 15, ty = tid >> 4;
    const int ia = ty * 4, ja = tx * 4;

    float acc[4][4] = {};
#pragma unroll
    for (int k = 0; k < D_; ++k) {
        float4 a  = *(const float4*)&Xs[k * SP + ia];
        float4 bb = *(const float4*)&Ys[k * SP + ja];
        float av[4] = {a.x, a.y, a.z, a.w};
        float bv[4] = {bb.x, bb.y, bb.z, bb.w};
#pragma unroll
        for (int r = 0; r < 4; ++r)
#pragma unroll
            for (int c = 0; c < 4; ++c)
                acc[r][c] = fmaf(av[r], bv[c], acc[r][c]);
    }

    float x2v[4], y2v[4];
#pragma unroll
    for (int r = 0; r < 4; ++r) x2v[r] = xn[ia + r];
#pragma unroll
    for (int c = 0; c < 4; ++c) y2v[c] = yn[ja + c];

    __syncthreads();
    float* Ts = Xs;   // reuse (needs 64*66 <= 64*68)

#pragma unroll
    for (int r = 0; r < 4; ++r)
#pragma unroll
        for (int c = 0; c < 4; ++c)
            Ts[(ia + r) * TSP + (ja + c)] =
                fmaf(-2.f, acc[r][c], x2v[r] + y2v[c]) * INV_LN2;
    __syncthreads();

    float* Dd = g_Dt + (size_t)b * (32 * 16 * 1024);
    const int kbase = i0 + j0;
#pragma unroll
    for (int it = 0; it < 16; ++it) {
        int f  = it * 256 + tid;                  // 0..4095
        int fr = (f < 2080) ? f : 4095 - f;
        int kl = (int)(0.5f * (sqrtf((float)(8 * fr + 1)) - 1.0f));
        if ((kl + 1) * (kl + 2) / 2 <= fr) kl++;
        if (kl * (kl + 1) / 2 > fr)       kl--;
        int tt = fr - kl * (kl + 1) / 2;
        int i, kg;
        if (f < 2080) { kg = kl;       i = tt;      }
        else          { kg = 126 - kl; i = 63 - tt; }
        int j   = kg - i;
        int kD  = kbase + kg;
        int row = i0 + i;
        Dd[((((kD >> 5) << 4) + (row >> 5)) << 10) + ((kD & 31) << 5) + (row & 31)]
            = Ts[i * TSP + j];
    }
}

// ---------------------------------------------------------------------------
// Kernel 2: soft-DTW, skewed row-pipeline, deferred-log softmin, tiled D feed.
// This round: branch-free inner step + mode-peeled rounds.
//   MODE 0 (rho==0):    head  — j<1 inactivity, j==1 column-0 seeds, R[0][0]
//   MODE 1 (1..15):     clean — no boundary logic at all
//   MODE 2 (rho==16):   tail  — j>512 deactivation only
// Ring is float2 (q,s); all lanes issue one broadcast LDS.64 per step and SEL
// it into lane 0 (row 16 of the ring is a constant BIGQ row used when w==0).
// Boundary publish is a single predicated STS.64 from lane 31.
// ---------------------------------------------------------------------------
#define WARPS_  16
#define RC      32            // steps per round (barrier period)
#define NROUNDS 47            // last active round = 2*15+16 = 46

template <int MODE>
__device__ __forceinline__ void round_body(
    int Tb0, int l, bool p0, bool p31, bool w0l0,
    const float2* __restrict__ ringrd, float2* __restrict__ ringwr,
    const float* __restrict__ dcur,
    float& q2, float& s2, float& hq, float& hs)
{
#pragma unroll
    for (int c = 0; c < RC; ++c) {
        const int Tp = Tb0 + c;

        float sq = __shfl_up_sync(0xffffffffu, q2, 1);
        float ss = __shfl_up_sync(0xffffffffu, s2, 1);
        float2 rv = ringrd[Tp & 127];          // broadcast LDS.64
        if (p0) { sq = rv.x; ss = rv.y; }      // SELs

        float q1 = sq, s1 = ss;                // R[i-1][j]
        float q0 = hq, s0 = hs;                // R[i-1][j-1]
        float qc = q2, sc = s2;                // R[i][j-1]

        if (MODE == 0) {
            const int j = Tp - l;
            if (j == 1) { q0 = BIGQ; s0 = 1.f; qc = BIGQ; sc = 1.f; }
            if (w0l0) {
                q1 = BIGQ; s1 = 1.f;
                q0 = (j == 1) ? 0.f : BIGQ; s0 = 1.f;
            }
        }

        float m  = fminf(fminf(q0, qc), q1);
        float e0 = ex2f(m - q0);
        float e1 = ex2f(m - q1);
        float e2 = ex2f(m - qc);
        float sn = fmaf(s0, e0, fmaf(s1, e1, sc * e2));
        float qn = dcur[c] + m;

        bool act = true;
        if (MODE == 0) act = (Tp - l) >= 1;
        if (MODE == 2) act = (Tp - l) <= M_;
        if (act) { q2 = qn; s2 = sn; }         // SELs
        hq = sq; hs = ss;

        bool wr = p31;
        if (MODE == 0 || MODE == 2) wr = p31 && act;
        if (wr) ringwr[(Tp - 31) & 127] = make_float2(q2, s2);  // @p STS.64
    }
    // value-preserving renorm keeps s in fp32 range (s >= 1 in-round)
    q2 -= lg2f(s2);
    s2 = 1.f;
}

__global__ void __launch_bounds__(512, 1) dtw_kernel(float* __restrict__ out) {
    __shared__ float2 ring[WARPS_ + 1][128];   // row 16 = constant BIGQ row

    const int b   = blockIdx.x;
    const int tid = threadIdx.x;
    const int w   = tid >> 5;
    const int l   = tid & 31;
    const float* Dbase = g_Dt + (size_t)b * (32 * 16 * 1024);

    // constant source row for warp 0's "previous boundary"
    if (tid < 128) ring[WARPS_][tid] = make_float2(BIGQ, 1.f);

    const bool  p0   = (l == 0);
    const bool  p31  = (l == 31);
    const bool  w0l0 = (w == 0) && (l == 0);
    const float2* ringrd = (w == 0) ? ring[WARPS_] : ring[w - 1];
    float2*       ringwr = ring[w];

    float q2 = BIGQ, s2 = 1.f;              // own R[i][j-1]
    float hq = BIGQ, hs = 1.f;              // held r1 from prev step -> r0 now
    float dcur[RC], dnxt[RC];

    // Preload warp 0's first tile (kt=0, wt=0).
    if (w == 0) {
        const float* tp = Dbase + l;
#pragma unroll
        for (int c = 0; c < RC; ++c) dcur[c] = __ldg(tp + c * 32);
    }
    __syncthreads();                        // ring row 16 visible

    for (int r = 0; r < NROUNDS; ++r) {
        const int  rho     = r - 2 * w;
        const bool act_nxt = (r + 1 >= 2 * w) && (r + 1 <= 2 * w + 16);

        // Prefetch next round's tile: 32 independent coalesced LDGs.
        if (act_nxt) {
            const float* tp = Dbase + (((size_t)(r + 1 - w) * 16 + w) << 10) + l;
#pragma unroll
            for (int c = 0; c < RC; ++c) dnxt[c] = __ldg(tp + c * 32);
        }

        const int Tb0 = 32 * r + 1 - 64 * w;
        if (rho == 0)
            round_body<0>(Tb0, l, p0, p31, w0l0, ringrd, ringwr, dcur, q2, s2, hq, hs);
        else if (rho >= 1 && rho <= 15)
            round_body<1>(Tb0, l, p0, p31, w0l0, ringrd, ringwr, dcur, q2, s2, hq, hs);
        else if (rho == 16)
            round_body<2>(Tb0, l, p0, p31, w0l0, ringrd, ringwr, dcur, q2, s2, hq, hs);

        if (act_nxt) {
#pragma unroll
            for (int c = 0; c < RC; ++c) dcur[c] = dnxt[c];
        }
        __syncthreads();
    }

    if (w == WARPS_ - 1 && l == 31)
        out[b] = (q2 - lg2f(s2)) * LN2;     // R[512][512]
}

// ---------------------------------------------------------------------------
extern "C" void kernel_launch(void* const* d_in, const int* in_sizes, int n_in,
                              void* d_out, int out_size) {
    const float* x = (const float*)d_in[0];
    const float* y = (const float*)d_in[1];
    float* out = (float*)d_out;

    dim3 dgrid(M_ / TS, N_ / TS, B_);
    dist_kernel<<<dgrid, 256>>>(x, y);
    dtw_kernel<<<B_, 512>>>(out);
}

// round 13
// speedup vs baseline: 1.8326x; 1.8326x over previous
#include <cuda_runtime.h>

#define B_   32
#define N_   512
#define M_   512
#define D_   64
#define BIGF 1e10f
#define INV_LN2 1.4426950408889634f
#define LN2     0.6931471805599453f
#define BIGQ (BIGF * INV_LN2)

// Feed: g_F[((b*8+w)*2+p)*FSTRIDE + s*32 + l], row = 64w+2l+p, s = col + l.
#define FSTRIDE (544 * 32)
__device__ float g_F[(size_t)B_ * 8 * 2 * FSTRIDE];

__device__ __forceinline__ float ex2f(float x) {
    float y; asm("ex2.approx.ftz.f32 %0, %1;" : "=f"(y) : "f"(x)); return y;
}
__device__ __forceinline__ float lg2f(float x) {
    float y; asm("lg2.approx.ftz.f32 %0, %1;" : "=f"(y) : "f"(x)); return y;
}

#define TS  64
#define SP  68
#define TSP 66

__global__ __launch_bounds__(256) void dist_kernel(const float* __restrict__ x,
                                                   const float* __restrict__ y) {
    __shared__ float Xs[D_ * SP];
    __shared__ float Ys[D_ * SP];
    __shared__ float xn[TS], yn[TS];

    const int b  = blockIdx.z;
    const int i0 = blockIdx.y * TS;
    const int j0 = blockIdx.x * TS;
    const float* xb = x + ((size_t)b * N_ + i0) * D_;
    const float* yb = y + ((size_t)b * M_ + j0) * D_;
    const int tid = threadIdx.x;

#pragma unroll
    for (int it = 0; it < 4; ++it) {
        int f = tid + it * 256, row = f & 63, c4 = f >> 6;
        float4 vx = *(const float4*)(xb + row * D_ + c4 * 4);
        float4 vy = *(const float4*)(yb + row * D_ + c4 * 4);
        Xs[(c4*4+0)*SP+row] = vx.x; Xs[(c4*4+1)*SP+row] = vx.y;
        Xs[(c4*4+2)*SP+row] = vx.z; Xs[(c4*4+3)*SP+row] = vx.w;
        Ys[(c4*4+0)*SP+row] = vy.x; Ys[(c4*4+1)*SP+row] = vy.y;
        Ys[(c4*4+2)*SP+row] = vy.z; Ys[(c4*4+3)*SP+row] = vy.w;
    }
    __syncthreads();

    if (tid < 64) {
        float s = 0.f;
#pragma unroll
        for (int k = 0; k < D_; ++k) { float v = Xs[k*SP+tid]; s = fmaf(v, v, s); }
        xn[tid] = s;
    } else if (tid < 128) {
        int r = tid - 64; float s = 0.f;
#pragma unroll
        for (int k = 0; k < D_; ++k) { float v = Ys[k*SP+r]; s = fmaf(v, v, s); }
        yn[r] = s;
    }
    __syncthreads();

    const int tx = tid & 15, ty = tid >> 4;
    const int ia = ty * 4, ja = tx * 4;
    float acc[4][4] = {};
#pragma unroll
    for (int k = 0; k < D_; ++k) {
        float4 a  = *(const float4*)&Xs[k*SP+ia];
        float4 bb = *(const float4*)&Ys[k*SP+ja];
        float av[4] = {a.x,a.y,a.z,a.w}, bv[4] = {bb.x,bb.y,bb.z,bb.w};
#pragma unroll
        for (int r = 0; r < 4; ++r)
#pragma unroll
            for (int c = 0; c < 4; ++c)
                acc[r][c] = fmaf(av[r], bv[c], acc[r][c]);
    }
    float x2v[4], y2v[4];
#pragma unroll
    for (int r = 0; r < 4; ++r) x2v[r] = xn[ia+r];
#pragma unroll
    for (int c = 0; c < 4; ++c) y2v[c] = yn[ja+c];

    __syncthreads();
    float* Ts = Xs;
#pragma unroll
    for (int r = 0; r < 4; ++r)
#pragma unroll
        for (int c = 0; c < 4; ++c)
            Ts[(ia+r)*TSP + ja+c] = fmaf(-2.f, acc[r][c], x2v[r]+y2v[c]) * INV_LN2;
    __syncthreads();

    // Drain: (row=2l+p, col=lv) -> g_F[(b*8+wD)*2+p][(j0+s_rel)*32+l], s_rel = lv+l.
    const int wD = blockIdx.y, wd = tid >> 5, l = tid & 31;
    float* F0 = g_F + ((size_t)(b * 8 + wD) * 2) * FSTRIDE;
#pragma unroll
    for (int p = 0; p < 2; ++p) {
        float* Fp = F0 + p * FSTRIDE;
#pragma unroll
        for (int it = 0; it < 16; ++it) {
            int s_rel = it * 8 + wd;          // 0..127; LDS banks 3l+c -> conflict-free
            int lv = s_rel - l;
            if (lv >= 0 && lv < 64)
                Fp[(j0 + s_rel) * 32 + l] = Ts[(2*l+p)*TSP + lv];
        }
    }
}

// ---------------------------------------------------------------------------
// soft-DTW: 8 warps/batch; lane l of warp w owns rows 64w+2l+1, 64w+2l+2.
// Deferred-log (q,s) state, exact select-form softmin (2 ex2/cell).
// 31 rounds x 32 steps; step T=32*rho+c, column j=T-l+1. Warp lag 2 rounds.
// ---------------------------------------------------------------------------
#define NR2 31

template <int MODE, int COFF>   // MODE: 0 head, 1 clean, 2 tail
__device__ __forceinline__ void half16(
    int rbase, int l, bool p0, bool p31, bool w0l0,
    const float2* __restrict__ ringrd, float2* __restrict__ ringwr,
    const float* __restrict__ dA, const float* __restrict__ dB,
    float& qT, float& sT, float& qB, float& sB, float& hq, float& hs)
{
#pragma unroll
    for (int cc = 0; cc < 16; ++cc) {
        const int c = COFF + cc;

        float sq = __shfl_up_sync(0xffffffffu, qB, 1);
        float ss = __shfl_up_sync(0xffffffffu, sB, 1);
        if (p0) { float2 rv = ringrd[(rbase + cc) & 127]; sq = rv.x; ss = rv.y; }

        float oqT = qT, osT = sT;

        // top cell: r0=(hq,hs)->R[i-1][j-1], r1=(sq,ss)->R[i-1][j], r2=(qT,sT)
        float q0 = hq, s0 = hs;
        if (MODE == 0 && c == 0 && w0l0) { q0 = 0.f; s0 = 1.f; }   // R[0][0]
        float lo = fminf(q0, qT), hi = fmaxf(q0, qT);
        float sl = (q0 <= qT) ? s0 : sT;
        float sh = (q0 <= qT) ? sT : s0;
        float pp = fmaf(sh, ex2f(lo - hi), sl);
        float m  = fminf(lo, sq);
        float e  = ex2f(m - fmaxf(lo, sq));
        float t1 = (sq < lo) ? pp : ss;
        float t2 = (sq < lo) ? ss : pp;
        float snT = fmaf(t1, e, t2);
        float qnT = dA[cc] + m;

        // bottom cell: r0=(oqT,osT), r1=(qnT,snT), r2=(qB,sB)
        float lob = fminf(oqT, qB), hib = fmaxf(oqT, qB);
        float slb = (oqT <= qB) ? osT : sB;
        float shb = (oqT <= qB) ? sB : osT;
        float ppb = fmaf(shb, ex2f(lob - hib), slb);
        float mb  = fminf(lob, qnT);
        float eb  = ex2f(mb - fmaxf(lob, qnT));
        float u1 = (qnT < lob) ? ppb : snT;
        float u2 = (qnT < lob) ? snT : ppb;
        float snB = fmaf(u1, eb, u2);
        float qnB = dB[cc] + mb;

        bool actc = true;
        if (MODE == 0) actc = (c >= l);
        if (MODE == 2) actc = (c < l);
        if (actc) { qT = qnT; sT = snT; qB = qnB; sB = snB; }
        hq = sq; hs = ss;

        bool wr = p31 && (MODE == 1 || actc);
        if (wr) ringwr[(rbase + cc - 31) & 127] = make_float2(qB, sB);
    }
}

__global__ void __launch_bounds__(256, 1) dtw_kernel(float* __restrict__ out) {
    __shared__ float2 ring[9][128];          // row 8 = constant BIGQ row

    const int b   = blockIdx.x;
    const int tid = threadIdx.x;
    const int w   = tid >> 5;
    const int l   = tid & 31;

    if (tid < 128) ring[8][tid] = make_float2(BIGQ, 1.f);

    const bool p0   = (l == 0);
    const bool p31  = (l == 31);
    const bool w0l0 = (w == 0) && (l == 0);
    const float2* ringrd = (w == 0) ? ring[8] : ring[w - 1];
    float2*       ringwr = ring[w];

    const float* FT = g_F + ((size_t)(b * 8 + w) * 2) * FSTRIDE + l;
    const float* FB = FT + FSTRIDE;

    float qT = BIGQ, sT = 1.f, qB = BIGQ, sB = 1.f;
    float hq = BIGQ, hs = 1.f;
    float a0[16], b0[16], a1[16], b1[16];

    if (w == 0) {
#pragma unroll
        for (int c = 0; c < 16; ++c) { a0[c] = __ldg(FT + c*32); b0[c] = __ldg(FB + c*32); }
    }
    __syncthreads();

    for (int r = 0; r < NR2; ++r) {
        const int rho = r - 2 * w;
        if (rho >= 0 && rho <= 16) {
            const int sb = rho * 32;
            // prefetch half1 of this round
#pragma unroll
            for (int c = 0; c < 16; ++c) {
                a1[c] = __ldg(FT + (sb + 16 + c)*32);
                b1[c] = __ldg(FB + (sb + 16 + c)*32);
            }
            const int rbase = sb + 1;
            if (rho == 0)
                half16<0, 0>(rbase, l, p0, p31, w0l0, ringrd, ringwr, a0, b0, qT, sT, qB, sB, hq, hs);
            else if (rho < 16)
                half16<1, 0>(rbase, l, p0, p31, w0l0, ringrd, ringwr, a0, b0, qT, sT, qB, sB, hq, hs);
            else
                half16<2, 0>(rbase, l, p0, p31, w0l0, ringrd, ringwr, a0, b0, qT, sT, qB, sB, hq, hs);

            if (rho < 16) {   // prefetch next round half0
#pragma unroll
                for (int c = 0; c < 16; ++c) {
                    a0[c] = __ldg(FT + (sb + 32 + c)*32);
                    b0[c] = __ldg(FB + (sb + 32 + c)*32);
                }
            }
            if (rho == 0)
                half16<0, 16>(rbase + 16, l, p0, p31, w0l0, ringrd, ringwr, a1, b1, qT, sT, qB, sB, hq, hs);
            else if (rho < 16)
                half16<1, 16>(rbase + 16, l, p0, p31, w0l0, ringrd, ringwr, a1, b1, qT, sT, qB, sB, hq, hs);
            else
                half16<2, 16>(rbase + 16, l, p0, p31, w0l0, ringrd, ringwr, a1, b1, qT, sT, qB, sB, hq, hs);

            qT -= lg2f(sT); sT = 1.f;        // value-preserving renorm
            qB -= lg2f(sB); sB = 1.f;
        } else if (rho == -1) {              // prime half0 of my first round
#pragma unroll
            for (int c = 0; c < 16; ++c) { a0[c] = __ldg(FT + c*32); b0[c] = __ldg(FB + c*32); }
        }
        __syncthreads();
    }

    if (w == 7 && l == 31)
        out[b] = (qB - lg2f(sB)) * LN2;      // R[512][512]
}

extern "C" void kernel_launch(void* const* d_in, const int* in_sizes, int n_in,
                              void* d_out, int out_size) {
    const float* x = (const float*)d_in[0];
    const float* y = (const float*)d_in[1];
    float* out = (float*)d_out;

    dim3 dgrid(M_ / TS, N_ / TS, B_);
    dist_kernel<<<dgrid, 256>>>(x, y);
    dtw_kernel<<<B_, 256>>>(out);
}